// round 16
// baseline (speedup 1.0000x reference)
#include <cuda_runtime.h>
#include <cuda_fp16.h>
#include <cstdint>

// ---------------------------------------------------------------------------
// GIN on GB300 (compute_103-portable):
//   aggregation: CSR build (hist with fused block-bins -> 2 scan kernels ->
//                fill) + warp-per-node fp16 gathers (fp32 accumulate)
//   GEMMs: pure fp16 mma.sync (fp32 accumulate), 2-stage cp.async pipeline,
//          static smem (R14-proven shape), K/N compile-time specialized
//   rel_err budget ~4e-4 (gate 1e-3)
// ---------------------------------------------------------------------------

#define N_NODES 50000
#define M_PAD   50048      // 128 * 391
#define D_MAX   256
#define E_MAX   (1 << 20)
#define NB_SCAN 196        // ceil(N_NODES / 256)

// Static scratch. Padding rows of g_a/g_b may hold stale data; they only
// influence GEMM output rows >= N_NODES, which are never stored.
__device__ __half g_xh[(size_t)N_NODES * 128];         // fp16 copy of x
__device__ __half g_a[(size_t)M_PAD * D_MAX];          // GEMM operand ping
__device__ __half g_b[(size_t)M_PAD * D_MAX];          // GEMM operand pong
__device__ __half g_wt[4][256 * 256];                  // transposed weights [N][K]
__device__ int g_deg[N_NODES];
__device__ int g_off[N_NODES + 1];
__device__ int g_pos[N_NODES];
__device__ int g_csr[E_MAX];
__device__ int g_bsum[256];
__device__ int g_boff[256];
__device__ int g_idx_is64;

// ---------------------------------------------------------------------------
// PTX helpers (portable: ldmatrix + mma.sync + cp.async, sm_80+)
// ---------------------------------------------------------------------------
static __device__ __forceinline__ uint32_t smem_u32(const void* p) {
    uint32_t a;
    asm("{ .reg .u64 t; cvta.to.shared.u64 t, %1; cvt.u32.u64 %0, t; }" : "=r"(a) : "l"(p));
    return a;
}

static __device__ __forceinline__ void ldsm_x4(uint32_t* r, uint32_t addr) {
    asm volatile("ldmatrix.sync.aligned.m8n8.x4.shared.b16 {%0,%1,%2,%3}, [%4];"
                 : "=r"(r[0]), "=r"(r[1]), "=r"(r[2]), "=r"(r[3]) : "r"(addr));
}

static __device__ __forceinline__ void mma16816(float* c, const uint32_t* a, const uint32_t* b) {
    asm volatile("mma.sync.aligned.m16n8k16.row.col.f32.f16.f16.f32 "
                 "{%0,%1,%2,%3}, {%4,%5,%6,%7}, {%8,%9}, {%0,%1,%2,%3};"
                 : "+f"(c[0]), "+f"(c[1]), "+f"(c[2]), "+f"(c[3])
                 : "r"(a[0]), "r"(a[1]), "r"(a[2]), "r"(a[3]), "r"(b[0]), "r"(b[1]));
}

static __device__ __forceinline__ void cp16(uint32_t saddr, const void* gaddr) {
    asm volatile("cp.async.ca.shared.global [%0], [%1], 16;"
                 :: "r"(saddr), "l"(gaddr) : "memory");
}
#define CP_COMMIT()  asm volatile("cp.async.commit_group;" ::: "memory")
#define CP_WAIT(N)   asm volatile("cp.async.wait_group %0;" :: "n"(N) : "memory")

// Fetch edge endpoint pair (src, dst) for edge e, handling int64/int32 data.
static __device__ __forceinline__ void edge_pair(const void* ei, int e, int E, int& s, int& d) {
    if (g_idx_is64) {
        const long long* p = (const long long*)ei;
        s = (int)p[e];
        d = (int)p[e + E];
    } else {
        const int* p = (const int*)ei;
        s = p[e];
        d = p[e + E];
    }
    s = min(max(s, 0), N_NODES - 1);
    d = min(max(d, 0), N_NODES - 1);
}

// ---------------------------------------------------------------------------
// setup: idx dtype + zero deg/bins + weight prep + x fp32->fp16 convert.
// Launch with 3125 blocks x 256 = 800000 threads (one per 8 x-elements).
// ---------------------------------------------------------------------------
__global__ void setup_kernel(const long long* __restrict__ ei,
                             const float* __restrict__ W1a, const float* __restrict__ W2a,
                             const float* __restrict__ W1b, const float* __restrict__ W2b,
                             __half* __restrict__ wt,
                             const float* __restrict__ x, __half* __restrict__ xh) {
    int i = blockIdx.x * blockDim.x + threadIdx.x;
    if (i == 0) {
        int is64 = 1;
        #pragma unroll 1
        for (int j = 0; j < 64; ++j) {
            long long v = ei[j];
            if (v < 0 || v >= (long long)N_NODES) { is64 = 0; break; }
        }
        g_idx_is64 = is64;
    }
    if (i < N_NODES) g_deg[i] = 0;
    if (i < 256) g_bsum[i] = 0;

    if (i < 196608) {
        const float* W; int K, N, base, li;
        if (i < 32768)       { W = W1a; K = 128; N = 256; base = 0;         li = i; }
        else if (i < 98304)  { W = W2a; K = 256; N = 256; base = 1 * 65536; li = i - 32768; }
        else if (i < 163840) { W = W1b; K = 256; N = 256; base = 2 * 65536; li = i - 98304; }
        else                 { W = W2b; K = 256; N = 128; base = 3 * 65536; li = i - 163840; }
        int n = li / K, k = li % K;
        wt[base + li] = __float2half(W[(size_t)k * N + n]);
    }

    // Convert 8 x-elements per thread: 50000*128/8 = 800000.
    if (i < 800000) {
        float4 v0 = reinterpret_cast<const float4*>(x)[i * 2];
        float4 v1 = reinterpret_cast<const float4*>(x)[i * 2 + 1];
        __half h[8];
        h[0] = __float2half(v0.x); h[1] = __float2half(v0.y);
        h[2] = __float2half(v0.z); h[3] = __float2half(v0.w);
        h[4] = __float2half(v1.x); h[5] = __float2half(v1.y);
        h[6] = __float2half(v1.z); h[7] = __float2half(v1.w);
        reinterpret_cast<uint4*>(xh)[i] = *reinterpret_cast<uint4*>(h);
    }
}

// ---------------------------------------------------------------------------
// CSR build: hist (deg + per-256-node bins) -> bin scan -> node scan -> fill.
// ---------------------------------------------------------------------------
__global__ void hist_kernel(const void* __restrict__ ei, int E) {
    int e = blockIdx.x * blockDim.x + threadIdx.x;
    if (e >= E) return;
    int s, d;
    edge_pair(ei, e, E, s, d);
    atomicAdd(&g_deg[d], 1);
    atomicAdd(&g_bsum[d >> 8], 1);
}

__global__ __launch_bounds__(256)
void scan_boff_kernel(int nb, int n) {
    __shared__ int s[256];
    int t = threadIdx.x;
    int v = (t < nb) ? g_bsum[t] : 0;
    s[t] = v;
    __syncthreads();
    #pragma unroll
    for (int ofs = 1; ofs < 256; ofs <<= 1) {
        int u = (t >= ofs) ? s[t - ofs] : 0;
        __syncthreads();
        s[t] += u;
        __syncthreads();
    }
    g_boff[t] = s[t] - v;                 // exclusive
    if (t == 255) g_off[n] = s[255];      // total edge count
}

__global__ __launch_bounds__(256)
void scan_write_kernel(int n) {
    __shared__ int s[256];
    int t = threadIdx.x;
    int i = blockIdx.x * 256 + t;
    int v = (i < n) ? g_deg[i] : 0;
    s[t] = v;
    __syncthreads();
    #pragma unroll
    for (int ofs = 1; ofs < 256; ofs <<= 1) {
        int u = (t >= ofs) ? s[t - ofs] : 0;
        __syncthreads();
        s[t] += u;
        __syncthreads();
    }
    if (i < n) {
        int off = g_boff[blockIdx.x] + s[t] - v;
        g_off[i] = off;
        g_pos[i] = off;
    }
}

__global__ void fill_kernel(const void* __restrict__ ei, int E) {
    int e = blockIdx.x * blockDim.x + threadIdx.x;
    if (e >= E) return;
    int s, d;
    edge_pair(ei, e, E, s, d);
    int slot = atomicAdd(&g_pos[d], 1);
    g_csr[slot] = s;
}

// ---------------------------------------------------------------------------
// Gathers: out[i] = feat[i] + sum_{j in N(i)} feat[j], fp16 in/out,
// fp32 accumulate. One warp per node, unroll 4.
// ---------------------------------------------------------------------------
// D=128: each lane owns 4 halves (8B).
__global__ void gather_h128(const __half* __restrict__ feat,
                            __half* __restrict__ outh, int n) {
    const int D = 128;
    int w = (blockIdx.x * blockDim.x + threadIdx.x) >> 5;
    const int lane = threadIdx.x & 31;
    if (w >= n) return;

    const int beg = g_off[w];
    const int end = g_off[w + 1];

    float acc[4];
    {
        uint2 v = *reinterpret_cast<const uint2*>(feat + (size_t)w * D + lane * 4);
        const __half2* p = reinterpret_cast<const __half2*>(&v);
        float2 f0 = __half22float2(p[0]), f1 = __half22float2(p[1]);
        acc[0] = f0.x; acc[1] = f0.y; acc[2] = f1.x; acc[3] = f1.y;
    }

    int i = beg;
    for (; i + 3 < end; i += 4) {
        int s0 = g_csr[i], s1 = g_csr[i + 1], s2 = g_csr[i + 2], s3 = g_csr[i + 3];
        uint2 va = *reinterpret_cast<const uint2*>(feat + (size_t)s0 * D + lane * 4);
        uint2 vb = *reinterpret_cast<const uint2*>(feat + (size_t)s1 * D + lane * 4);
        uint2 vc = *reinterpret_cast<const uint2*>(feat + (size_t)s2 * D + lane * 4);
        uint2 vd = *reinterpret_cast<const uint2*>(feat + (size_t)s3 * D + lane * 4);
        const __half2 *pa = (const __half2*)&va, *pb = (const __half2*)&vb;
        const __half2 *pc = (const __half2*)&vc, *pd = (const __half2*)&vd;
        #pragma unroll
        for (int j = 0; j < 2; ++j) {
            float2 fa = __half22float2(pa[j]), fb = __half22float2(pb[j]);
            float2 fc = __half22float2(pc[j]), fd = __half22float2(pd[j]);
            acc[j * 2 + 0] += (fa.x + fb.x) + (fc.x + fd.x);
            acc[j * 2 + 1] += (fa.y + fb.y) + (fc.y + fd.y);
        }
    }
    for (; i < end; ++i) {
        int s0 = g_csr[i];
        uint2 va = *reinterpret_cast<const uint2*>(feat + (size_t)s0 * D + lane * 4);
        const __half2* pa = (const __half2*)&va;
        #pragma unroll
        for (int j = 0; j < 2; ++j) {
            float2 fa = __half22float2(pa[j]);
            acc[j * 2 + 0] += fa.x;
            acc[j * 2 + 1] += fa.y;
        }
    }

    __half h[4];
    #pragma unroll
    for (int j = 0; j < 4; ++j) h[j] = __float2half(acc[j]);
    *reinterpret_cast<uint2*>(outh + (size_t)w * D + lane * 4) = *reinterpret_cast<uint2*>(h);
}

// D=256: each lane owns 8 halves (16B).
__global__ void gather_h256(const __half* __restrict__ feat,
                            __half* __restrict__ outh, int n) {
    const int D = 256;
    int w = (blockIdx.x * blockDim.x + threadIdx.x) >> 5;
    const int lane = threadIdx.x & 31;
    if (w >= n) return;

    const int beg = g_off[w];
    const int end = g_off[w + 1];

    float acc[8];
    {
        uint4 v = *reinterpret_cast<const uint4*>(feat + (size_t)w * D + lane * 8);
        const __half2* p = reinterpret_cast<const __half2*>(&v);
        #pragma unroll
        for (int j = 0; j < 4; ++j) {
            float2 f = __half22float2(p[j]);
            acc[j * 2 + 0] = f.x;
            acc[j * 2 + 1] = f.y;
        }
    }

    int i = beg;
    for (; i + 3 < end; i += 4) {
        int s0 = g_csr[i], s1 = g_csr[i + 1], s2 = g_csr[i + 2], s3 = g_csr[i + 3];
        uint4 va = *reinterpret_cast<const uint4*>(feat + (size_t)s0 * D + lane * 8);
        uint4 vb = *reinterpret_cast<const uint4*>(feat + (size_t)s1 * D + lane * 8);
        uint4 vc = *reinterpret_cast<const uint4*>(feat + (size_t)s2 * D + lane * 8);
        uint4 vd = *reinterpret_cast<const uint4*>(feat + (size_t)s3 * D + lane * 8);
        const __half2 *pa = (const __half2*)&va, *pb = (const __half2*)&vb;
        const __half2 *pc = (const __half2*)&vc, *pd = (const __half2*)&vd;
        #pragma unroll
        for (int j = 0; j < 4; ++j) {
            float2 fa = __half22float2(pa[j]), fb = __half22float2(pb[j]);
            float2 fc = __half22float2(pc[j]), fd = __half22float2(pd[j]);
            acc[j * 2 + 0] += (fa.x + fb.x) + (fc.x + fd.x);
            acc[j * 2 + 1] += (fa.y + fb.y) + (fc.y + fd.y);
        }
    }
    for (; i < end; ++i) {
        int s0 = g_csr[i];
        uint4 va = *reinterpret_cast<const uint4*>(feat + (size_t)s0 * D + lane * 8);
        const __half2* pa = (const __half2*)&va;
        #pragma unroll
        for (int j = 0; j < 4; ++j) {
            float2 fa = __half22float2(pa[j]);
            acc[j * 2 + 0] += fa.x;
            acc[j * 2 + 1] += fa.y;
        }
    }

    __half h[8];
    #pragma unroll
    for (int j = 0; j < 8; ++j) h[j] = __float2half(acc[j]);
    *reinterpret_cast<uint4*>(outh + (size_t)w * D + lane * 8) = *reinterpret_cast<uint4*>(h);
}

// ---------------------------------------------------------------------------
// mma.sync GEMM (R14-proven shape): C[M,N] = A[M,K]@B^T (A, B fp16; B
// transposed [N,K]). K, N compile-time; fp32 accumulate, single product.
// CTA tile 128x128, BK=32, 256 threads (8 warps, 2x4), warp tile 64x32.
// 2-stage cp.async pipeline, static smem 40KB.
// EPI: 0 = fp32 out (no relu), 1 = relu -> fp16.
// ---------------------------------------------------------------------------
template<int EPI, int K, int N>
__global__ __launch_bounds__(256)
void mma_gemm(const __half* __restrict__ A,
              const __half* __restrict__ Bt,
              const float* __restrict__ bias,
              float* __restrict__ outf,
              __half* __restrict__ outh,
              int M) {
    constexpr int BM = 128, BK = 32, LDS = BK + 8;   // pad -> conflict-free ldmatrix
    constexpr int KTILES = K / BK;
    __shared__ __half Ah[2][BM][LDS];
    __shared__ __half Bh[2][BM][LDS];

    const int tid  = threadIdx.x;
    const int wid  = tid >> 5;
    const int lane = tid & 31;
    const int bm = blockIdx.y * 128;
    const int bn = blockIdx.x * 128;

    const int wm = (wid >> 2) * 64;   // warp m offset: 0 or 64
    const int wn = (wid & 3) * 32;    // warp n offset: 0,32,64,96

    const int lane_r = lane & 15;          // ldmatrix row within 16-row group
    const int lane_c = (lane >> 4) * 8;    // k-half

    float acc[4][4][4];
    #pragma unroll
    for (int mf = 0; mf < 4; ++mf)
        #pragma unroll
        for (int nf = 0; nf < 4; ++nf)
            #pragma unroll
            for (int c = 0; c < 4; ++c)
                acc[mf][nf][c] = 0.0f;

    // Global load mapping: row = tid>>2 (0..63) + it*64, col = (tid&3)*8.
    const int g_row0 = tid >> 2;
    const int g_col  = (tid & 3) * 8;

    // Per-thread smem cp.async destinations (byte addresses).
    uint32_t s_ah[2][2], s_bh[2][2];
    #pragma unroll
    for (int b = 0; b < 2; ++b)
        #pragma unroll
        for (int it = 0; it < 2; ++it) {
            const int row = g_row0 + it * 64;
            s_ah[b][it] = smem_u32(&Ah[b][row][g_col]);
            s_bh[b][it] = smem_u32(&Bh[b][row][g_col]);
        }

    // Issue async loads for k-tile kt into buffer b.
    auto load_tile = [&](int kt, int b) {
        const int k0 = kt << 5;
        #pragma unroll
        for (int it = 0; it < 2; ++it) {
            const int row = g_row0 + it * 64;
            const size_t ga = (size_t)(bm + row) * K + k0 + g_col;
            const size_t gb = (size_t)(bn + row) * K + k0 + g_col;
            cp16(s_ah[b][it], A + ga);
            cp16(s_bh[b][it], Bt + gb);
        }
        CP_COMMIT();
    };

    // Prologue: tile 0 in flight.
    load_tile(0, 0);

    #pragma unroll
    for (int kt = 0; kt < KTILES; ++kt) {
        const int buf = kt & 1;

        if (kt + 1 < KTILES) {
            load_tile(kt + 1, buf ^ 1);
            CP_WAIT(1);      // tile kt complete; tile kt+1 may be in flight
        } else {
            CP_WAIT(0);
        }
        __syncthreads();

        const uint32_t ah_base = smem_u32(&Ah[buf][0][0]);
        const uint32_t bh_base = smem_u32(&Bh[buf][0][0]);

        #pragma unroll
        for (int ks = 0; ks < 2; ++ks) {
            const uint32_t a_off = (uint32_t)(ks * 16 + lane_c) * 2;

            uint32_t ah[4][4];
            #pragma unroll
            for (int mf = 0; mf < 4; ++mf) {
                const uint32_t ro = (uint32_t)((wm + mf * 16 + lane_r) * LDS) * 2;
                ldsm_x4(ah[mf], ah_base + ro + a_off);
            }
            uint32_t bh[4][2];
            #pragma unroll
            for (int np = 0; np < 2; ++np) {
                const uint32_t ro = (uint32_t)((wn + np * 16 + lane_r) * LDS) * 2;
                uint32_t r[4];
                ldsm_x4(r, bh_base + ro + a_off);
                bh[np * 2 + 0][0] = r[0]; bh[np * 2 + 0][1] = r[2];
                bh[np * 2 + 1][0] = r[1]; bh[np * 2 + 1][1] = r[3];
            }

            #pragma unroll
            for (int mf = 0; mf < 4; ++mf)
                #pragma unroll
                for (int nf = 0; nf < 4; ++nf)
                    mma16816(acc[mf][nf], ah[mf], bh[nf]);
        }
        __syncthreads();
    }

    // Epilogue. Thread owns rows (gr, gr+8), cols 2*(lane%4)+{0,1} per fragment.
    const int gr = lane >> 2;
    const int gc = (lane & 3) * 2;
    #pragma unroll
    for (int mf = 0; mf < 4; ++mf) {
        const int row0 = bm + wm + mf * 16 + gr;
        const int row1 = row0 + 8;
        #pragma unroll
        for (int nf = 0; nf < 4; ++nf) {
            const int col = bn + wn + nf * 8 + gc;
            const float bz0 = bias[col], bz1 = bias[col + 1];
            float v00 = acc[mf][nf][0] + bz0, v01 = acc[mf][nf][1] + bz1;
            float v10 = acc[mf][nf][2] + bz0, v11 = acc[mf][nf][3] + bz1;
            if (EPI == 1) {
                v00 = fmaxf(v00, 0.f); v01 = fmaxf(v01, 0.f);
                v10 = fmaxf(v10, 0.f); v11 = fmaxf(v11, 0.f);
                if (row0 < M) {
                    __half2 hh; hh.x = __float2half(v00); hh.y = __float2half(v01);
                    *reinterpret_cast<__half2*>(outh + (size_t)row0 * N + col) = hh;
                }
                if (row1 < M) {
                    __half2 hh; hh.x = __float2half(v10); hh.y = __float2half(v11);
                    *reinterpret_cast<__half2*>(outh + (size_t)row1 * N + col) = hh;
                }
            } else {
                if (row0 < M) {
                    float2 v; v.x = v00; v.y = v01;
                    *reinterpret_cast<float2*>(outf + (size_t)row0 * N + col) = v;
                }
                if (row1 < M) {
                    float2 v; v.x = v10; v.y = v11;
                    *reinterpret_cast<float2*>(outf + (size_t)row1 * N + col) = v;
                }
            }
        }
    }
}

// ---------------------------------------------------------------------------
// Launch
// ---------------------------------------------------------------------------
extern "C" void kernel_launch(void* const* d_in, const int* in_sizes, int n_in,
                              void* d_out, int out_size) {
    const float* x    = (const float*)d_in[0];
    const float* W1a  = (const float*)d_in[1];
    const float* b1a  = (const float*)d_in[2];
    const float* W2a  = (const float*)d_in[3];
    const float* b2a  = (const float*)d_in[4];
    const float* W1b  = (const float*)d_in[5];
    const float* b1b  = (const float*)d_in[6];
    const float* W2b  = (const float*)d_in[7];
    const float* b2b  = (const float*)d_in[8];
    const void*  ei   = d_in[9];

    const int M = N_NODES;
    const int E = in_sizes[9] / 2;

    __half *XH, *A, *B, *WT;
    cudaGetSymbolAddress((void**)&XH, g_xh);
    cudaGetSymbolAddress((void**)&A, g_a);
    cudaGetSymbolAddress((void**)&B, g_b);
    cudaGetSymbolAddress((void**)&WT, g_wt);

    float* out = (float*)d_out;
    const int GY = M_PAD / 128;   // 391

    // Setup (idx dtype + zero deg/bins + weight prep + x->fp16) + CSR build.
    setup_kernel<<<3125, 256>>>((const long long*)ei, W1a, W2a, W1b, W2b, WT, x, XH);
    hist_kernel<<<(E + 255) / 256, 256>>>(ei, E);
    scan_boff_kernel<<<1, 256>>>(NB_SCAN, N_NODES);
    scan_write_kernel<<<NB_SCAN, 256>>>(N_NODES);
    fill_kernel<<<(E + 255) / 256, 256>>>(ei, E);

    // ---- Layer 0 ----
    // A = fp16(x + gather(x))    (fp16 reads, fp32 accumulate)
    gather_h128<<<(M * 32 + 255) / 256, 256>>>(XH, A, M);
    // h1 = relu(A @ W1a + b1a) -> fp16 B      [50000,128]@[128,256]
    mma_gemm<1, 128, 256><<<dim3(2, GY), 256>>>(A, WT + 0 * 65536, b1a, nullptr, B, M);
    // h2 = relu(B @ W2a + b2a) -> fp16 A      [50000,256]@[256,256]
    mma_gemm<1, 256, 256><<<dim3(2, GY), 256>>>(B, WT + 1 * 65536, b2a, nullptr, A, M);

    // ---- Layer 1 ----
    // B = fp16(h2 + gather(h2))
    gather_h256<<<(M * 32 + 255) / 256, 256>>>(A, B, M);
    // h3 = relu(B @ W1b + b1b) -> fp16 A      [50000,256]@[256,256]
    mma_gemm<1, 256, 256><<<dim3(2, GY), 256>>>(B, WT + 2 * 65536, b1b, nullptr, A, M);
    // out = A @ W2b + b2b                     [50000,256]@[256,128]
    mma_gemm<0, 256, 128><<<dim3(1, GY), 256>>>(A, WT + 3 * 65536, b2b, out, nullptr, M);
}

// round 17
// speedup vs baseline: 1.4089x; 1.4089x over previous
#include <cuda_runtime.h>
#include <cuda_fp16.h>
#include <cstdint>

// ---------------------------------------------------------------------------
// GIN on GB300 (compute_103-portable):
//   aggregation: CSR build (hist -> coalesced 3-phase scan -> fill) +
//                warp-per-node fp16 gathers (fp32 accumulate)
//   GEMMs: pure fp16 mma.sync (fp32 accumulate), 2-stage cp.async pipeline,
//          static smem (R14-proven shape), K/N compile-time specialized
//   rel_err budget ~4e-4 (gate 1e-3)
// ---------------------------------------------------------------------------

#define N_NODES 50000
#define M_PAD   50048      // 128 * 391
#define D_MAX   256
#define E_MAX   (1 << 20)
#define NB_SCAN 196        // ceil(N_NODES / 256)

// Static scratch. Padding rows of g_a/g_b may hold stale data; they only
// influence GEMM output rows >= N_NODES, which are never stored.
__device__ __half g_xh[(size_t)N_NODES * 128];         // fp16 copy of x
__device__ __half g_a[(size_t)M_PAD * D_MAX];          // GEMM operand ping
__device__ __half g_b[(size_t)M_PAD * D_MAX];          // GEMM operand pong
__device__ __half g_wt[4][256 * 256];                  // transposed weights [N][K]
__device__ int g_deg[N_NODES];
__device__ int g_off[N_NODES + 1];
__device__ int g_pos[N_NODES];
__device__ int g_csr[E_MAX];
__device__ int g_bsum[256];
__device__ int g_boff[256];
__device__ int g_idx_is64;

// ---------------------------------------------------------------------------
// PTX helpers (portable: ldmatrix + mma.sync + cp.async, sm_80+)
// ---------------------------------------------------------------------------
static __device__ __forceinline__ uint32_t smem_u32(const void* p) {
    uint32_t a;
    asm("{ .reg .u64 t; cvta.to.shared.u64 t, %1; cvt.u32.u64 %0, t; }" : "=r"(a) : "l"(p));
    return a;
}

static __device__ __forceinline__ void ldsm_x4(uint32_t* r, uint32_t addr) {
    asm volatile("ldmatrix.sync.aligned.m8n8.x4.shared.b16 {%0,%1,%2,%3}, [%4];"
                 : "=r"(r[0]), "=r"(r[1]), "=r"(r[2]), "=r"(r[3]) : "r"(addr));
}

static __device__ __forceinline__ void mma16816(float* c, const uint32_t* a, const uint32_t* b) {
    asm volatile("mma.sync.aligned.m16n8k16.row.col.f32.f16.f16.f32 "
                 "{%0,%1,%2,%3}, {%4,%5,%6,%7}, {%8,%9}, {%0,%1,%2,%3};"
                 : "+f"(c[0]), "+f"(c[1]), "+f"(c[2]), "+f"(c[3])
                 : "r"(a[0]), "r"(a[1]), "r"(a[2]), "r"(a[3]), "r"(b[0]), "r"(b[1]));
}

static __device__ __forceinline__ void cp16(uint32_t saddr, const void* gaddr) {
    asm volatile("cp.async.ca.shared.global [%0], [%1], 16;"
                 :: "r"(saddr), "l"(gaddr) : "memory");
}
#define CP_COMMIT()  asm volatile("cp.async.commit_group;" ::: "memory")
#define CP_WAIT(N)   asm volatile("cp.async.wait_group %0;" :: "n"(N) : "memory")

// Fetch edge endpoint pair (src, dst) for edge e, handling int64/int32 data.
static __device__ __forceinline__ void edge_pair(const void* ei, int e, int E, int& s, int& d) {
    if (g_idx_is64) {
        const long long* p = (const long long*)ei;
        s = (int)p[e];
        d = (int)p[e + E];
    } else {
        const int* p = (const int*)ei;
        s = p[e];
        d = p[e + E];
    }
    s = min(max(s, 0), N_NODES - 1);
    d = min(max(d, 0), N_NODES - 1);
}

// ---------------------------------------------------------------------------
// setup: idx dtype + zero degrees + weight prep + x fp32->fp16 convert.
// Launch with 3125 blocks x 256 = 800000 threads (one per 8 x-elements).
// ---------------------------------------------------------------------------
__global__ void setup_kernel(const long long* __restrict__ ei,
                             const float* __restrict__ W1a, const float* __restrict__ W2a,
                             const float* __restrict__ W1b, const float* __restrict__ W2b,
                             __half* __restrict__ wt,
                             const float* __restrict__ x, __half* __restrict__ xh) {
    int i = blockIdx.x * blockDim.x + threadIdx.x;
    if (i == 0) {
        int is64 = 1;
        #pragma unroll 1
        for (int j = 0; j < 64; ++j) {
            long long v = ei[j];
            if (v < 0 || v >= (long long)N_NODES) { is64 = 0; break; }
        }
        g_idx_is64 = is64;
    }
    if (i < N_NODES) g_deg[i] = 0;

    if (i < 196608) {
        const float* W; int K, N, base, li;
        if (i < 32768)       { W = W1a; K = 128; N = 256; base = 0;         li = i; }
        else if (i < 98304)  { W = W2a; K = 256; N = 256; base = 1 * 65536; li = i - 32768; }
        else if (i < 163840) { W = W1b; K = 256; N = 256; base = 2 * 65536; li = i - 98304; }
        else                 { W = W2b; K = 256; N = 128; base = 3 * 65536; li = i - 163840; }
        int n = li / K, k = li % K;
        wt[base + li] = __float2half(W[(size_t)k * N + n]);
    }

    // Convert 8 x-elements per thread: 50000*128/8 = 800000.
    if (i < 800000) {
        float4 v0 = reinterpret_cast<const float4*>(x)[i * 2];
        float4 v1 = reinterpret_cast<const float4*>(x)[i * 2 + 1];
        __half h[8];
        h[0] = __float2half(v0.x); h[1] = __float2half(v0.y);
        h[2] = __float2half(v0.z); h[3] = __float2half(v0.w);
        h[4] = __float2half(v1.x); h[5] = __float2half(v1.y);
        h[6] = __float2half(v1.z); h[7] = __float2half(v1.w);
        reinterpret_cast<uint4*>(xh)[i] = *reinterpret_cast<uint4*>(h);
    }
}

// ---------------------------------------------------------------------------
// CSR build: hist -> 3-phase coalesced scan -> fill.  (R14-proven; the fused
// per-256-bin atomic in hist was a ~170us L2-atomic-contention disaster.)
// ---------------------------------------------------------------------------
__global__ void hist_kernel(const void* __restrict__ ei, int E) {
    int e = blockIdx.x * blockDim.x + threadIdx.x;
    if (e >= E) return;
    int s, d;
    edge_pair(ei, e, E, s, d);
    atomicAdd(&g_deg[d], 1);
}

__global__ __launch_bounds__(256)
void scan_bsum_kernel(int n) {
    __shared__ int red[256];
    int i = blockIdx.x * 256 + threadIdx.x;
    red[threadIdx.x] = (i < n) ? g_deg[i] : 0;
    __syncthreads();
    #pragma unroll
    for (int ofs = 128; ofs > 0; ofs >>= 1) {
        if (threadIdx.x < ofs) red[threadIdx.x] += red[threadIdx.x + ofs];
        __syncthreads();
    }
    if (threadIdx.x == 0) g_bsum[blockIdx.x] = red[0];
}

__global__ __launch_bounds__(256)
void scan_boff_kernel(int nb, int n) {
    __shared__ int s[256];
    int t = threadIdx.x;
    int v = (t < nb) ? g_bsum[t] : 0;
    s[t] = v;
    __syncthreads();
    #pragma unroll
    for (int ofs = 1; ofs < 256; ofs <<= 1) {
        int u = (t >= ofs) ? s[t - ofs] : 0;
        __syncthreads();
        s[t] += u;
        __syncthreads();
    }
    g_boff[t] = s[t] - v;                 // exclusive
    if (t == 255) g_off[n] = s[255];      // total edge count
}

__global__ __launch_bounds__(256)
void scan_write_kernel(int n) {
    __shared__ int s[256];
    int t = threadIdx.x;
    int i = blockIdx.x * 256 + t;
    int v = (i < n) ? g_deg[i] : 0;
    s[t] = v;
    __syncthreads();
    #pragma unroll
    for (int ofs = 1; ofs < 256; ofs <<= 1) {
        int u = (t >= ofs) ? s[t - ofs] : 0;
        __syncthreads();
        s[t] += u;
        __syncthreads();
    }
    if (i < n) {
        int off = g_boff[blockIdx.x] + s[t] - v;
        g_off[i] = off;
        g_pos[i] = off;
    }
}

__global__ void fill_kernel(const void* __restrict__ ei, int E) {
    int e = blockIdx.x * blockDim.x + threadIdx.x;
    if (e >= E) return;
    int s, d;
    edge_pair(ei, e, E, s, d);
    int slot = atomicAdd(&g_pos[d], 1);
    g_csr[slot] = s;
}

// ---------------------------------------------------------------------------
// Gathers: out[i] = feat[i] + sum_{j in N(i)} feat[j], fp16 in/out,
// fp32 accumulate. One warp per node, unroll 4.
// ---------------------------------------------------------------------------
// D=128: each lane owns 4 halves (8B).
__global__ void gather_h128(const __half* __restrict__ feat,
                            __half* __restrict__ outh, int n) {
    const int D = 128;
    int w = (blockIdx.x * blockDim.x + threadIdx.x) >> 5;
    const int lane = threadIdx.x & 31;
    if (w >= n) return;

    const int beg = g_off[w];
    const int end = g_off[w + 1];

    float acc[4];
    {
        uint2 v = *reinterpret_cast<const uint2*>(feat + (size_t)w * D + lane * 4);
        const __half2* p = reinterpret_cast<const __half2*>(&v);
        float2 f0 = __half22float2(p[0]), f1 = __half22float2(p[1]);
        acc[0] = f0.x; acc[1] = f0.y; acc[2] = f1.x; acc[3] = f1.y;
    }

    int i = beg;
    for (; i + 3 < end; i += 4) {
        int s0 = g_csr[i], s1 = g_csr[i + 1], s2 = g_csr[i + 2], s3 = g_csr[i + 3];
        uint2 va = *reinterpret_cast<const uint2*>(feat + (size_t)s0 * D + lane * 4);
        uint2 vb = *reinterpret_cast<const uint2*>(feat + (size_t)s1 * D + lane * 4);
        uint2 vc = *reinterpret_cast<const uint2*>(feat + (size_t)s2 * D + lane * 4);
        uint2 vd = *reinterpret_cast<const uint2*>(feat + (size_t)s3 * D + lane * 4);
        const __half2 *pa = (const __half2*)&va, *pb = (const __half2*)&vb;
        const __half2 *pc = (const __half2*)&vc, *pd = (const __half2*)&vd;
        #pragma unroll
        for (int j = 0; j < 2; ++j) {
            float2 fa = __half22float2(pa[j]), fb = __half22float2(pb[j]);
            float2 fc = __half22float2(pc[j]), fd = __half22float2(pd[j]);
            acc[j * 2 + 0] += (fa.x + fb.x) + (fc.x + fd.x);
            acc[j * 2 + 1] += (fa.y + fb.y) + (fc.y + fd.y);
        }
    }
    for (; i < end; ++i) {
        int s0 = g_csr[i];
        uint2 va = *reinterpret_cast<const uint2*>(feat + (size_t)s0 * D + lane * 4);
        const __half2* pa = (const __half2*)&va;
        #pragma unroll
        for (int j = 0; j < 2; ++j) {
            float2 fa = __half22float2(pa[j]);
            acc[j * 2 + 0] += fa.x;
            acc[j * 2 + 1] += fa.y;
        }
    }

    __half h[4];
    #pragma unroll
    for (int j = 0; j < 4; ++j) h[j] = __float2half(acc[j]);
    *reinterpret_cast<uint2*>(outh + (size_t)w * D + lane * 4) = *reinterpret_cast<uint2*>(h);
}

// D=256: each lane owns 8 halves (16B).
__global__ void gather_h256(const __half* __restrict__ feat,
                            __half* __restrict__ outh, int n) {
    const int D = 256;
    int w = (blockIdx.x * blockDim.x + threadIdx.x) >> 5;
    const int lane = threadIdx.x & 31;
    if (w >= n) return;

    const int beg = g_off[w];
    const int end = g_off[w + 1];

    float acc[8];
    {
        uint4 v = *reinterpret_cast<const uint4*>(feat + (size_t)w * D + lane * 8);
        const __half2* p = reinterpret_cast<const __half2*>(&v);
        #pragma unroll
        for (int j = 0; j < 4; ++j) {
            float2 f = __half22float2(p[j]);
            acc[j * 2 + 0] = f.x;
            acc[j * 2 + 1] = f.y;
        }
    }

    int i = beg;
    for (; i + 3 < end; i += 4) {
        int s0 = g_csr[i], s1 = g_csr[i + 1], s2 = g_csr[i + 2], s3 = g_csr[i + 3];
        uint4 va = *reinterpret_cast<const uint4*>(feat + (size_t)s0 * D + lane * 8);
        uint4 vb = *reinterpret_cast<const uint4*>(feat + (size_t)s1 * D + lane * 8);
        uint4 vc = *reinterpret_cast<const uint4*>(feat + (size_t)s2 * D + lane * 8);
        uint4 vd = *reinterpret_cast<const uint4*>(feat + (size_t)s3 * D + lane * 8);
        const __half2 *pa = (const __half2*)&va, *pb = (const __half2*)&vb;
        const __half2 *pc = (const __half2*)&vc, *pd = (const __half2*)&vd;
        #pragma unroll
        for (int j = 0; j < 4; ++j) {
            float2 fa = __half22float2(pa[j]), fb = __half22float2(pb[j]);
            float2 fc = __half22float2(pc[j]), fd = __half22float2(pd[j]);
            acc[j * 2 + 0] += (fa.x + fb.x) + (fc.x + fd.x);
            acc[j * 2 + 1] += (fa.y + fb.y) + (fc.y + fd.y);
        }
    }
    for (; i < end; ++i) {
        int s0 = g_csr[i];
        uint4 va = *reinterpret_cast<const uint4*>(feat + (size_t)s0 * D + lane * 8);
        const __half2* pa = (const __half2*)&va;
        #pragma unroll
        for (int j = 0; j < 4; ++j) {
            float2 fa = __half22float2(pa[j]);
            acc[j * 2 + 0] += fa.x;
            acc[j * 2 + 1] += fa.y;
        }
    }

    __half h[8];
    #pragma unroll
    for (int j = 0; j < 8; ++j) h[j] = __float2half(acc[j]);
    *reinterpret_cast<uint4*>(outh + (size_t)w * D + lane * 8) = *reinterpret_cast<uint4*>(h);
}

// ---------------------------------------------------------------------------
// mma.sync GEMM (R14-proven shape): C[M,N] = A[M,K]@B^T (A, B fp16; B
// transposed [N,K]). K, N compile-time; fp32 accumulate, single product.
// CTA tile 128x128, BK=32, 256 threads (8 warps, 2x4), warp tile 64x32.
// 2-stage cp.async pipeline, static smem 40KB.
// EPI: 0 = fp32 out (no relu), 1 = relu -> fp16.
// ---------------------------------------------------------------------------
template<int EPI, int K, int N>
__global__ __launch_bounds__(256)
void mma_gemm(const __half* __restrict__ A,
              const __half* __restrict__ Bt,
              const float* __restrict__ bias,
              float* __restrict__ outf,
              __half* __restrict__ outh,
              int M) {
    constexpr int BM = 128, BK = 32, LDS = BK + 8;   // pad -> conflict-free ldmatrix
    constexpr int KTILES = K / BK;
    __shared__ __half Ah[2][BM][LDS];
    __shared__ __half Bh[2][BM][LDS];

    const int tid  = threadIdx.x;
    const int wid  = tid >> 5;
    const int lane = tid & 31;
    const int bm = blockIdx.y * 128;
    const int bn = blockIdx.x * 128;

    const int wm = (wid >> 2) * 64;   // warp m offset: 0 or 64
    const int wn = (wid & 3) * 32;    // warp n offset: 0,32,64,96

    const int lane_r = lane & 15;          // ldmatrix row within 16-row group
    const int lane_c = (lane >> 4) * 8;    // k-half

    float acc[4][4][4];
    #pragma unroll
    for (int mf = 0; mf < 4; ++mf)
        #pragma unroll
        for (int nf = 0; nf < 4; ++nf)
            #pragma unroll
            for (int c = 0; c < 4; ++c)
                acc[mf][nf][c] = 0.0f;

    // Global load mapping: row = tid>>2 (0..63) + it*64, col = (tid&3)*8.
    const int g_row0 = tid >> 2;
    const int g_col  = (tid & 3) * 8;

    // Per-thread smem cp.async destinations (byte addresses).
    uint32_t s_ah[2][2], s_bh[2][2];
    #pragma unroll
    for (int b = 0; b < 2; ++b)
        #pragma unroll
        for (int it = 0; it < 2; ++it) {
            const int row = g_row0 + it * 64;
            s_ah[b][it] = smem_u32(&Ah[b][row][g_col]);
            s_bh[b][it] = smem_u32(&Bh[b][row][g_col]);
        }

    // Issue async loads for k-tile kt into buffer b.
    auto load_tile = [&](int kt, int b) {
        const int k0 = kt << 5;
        #pragma unroll
        for (int it = 0; it < 2; ++it) {
            const int row = g_row0 + it * 64;
            const size_t ga = (size_t)(bm + row) * K + k0 + g_col;
            const size_t gb = (size_t)(bn + row) * K + k0 + g_col;
            cp16(s_ah[b][it], A + ga);
            cp16(s_bh[b][it], Bt + gb);
        }
        CP_COMMIT();
    };

    // Prologue: tile 0 in flight.
    load_tile(0, 0);

    #pragma unroll
    for (int kt = 0; kt < KTILES; ++kt) {
        const int buf = kt & 1;

        if (kt + 1 < KTILES) {
            load_tile(kt + 1, buf ^ 1);
            CP_WAIT(1);      // tile kt complete; tile kt+1 may be in flight
        } else {
            CP_WAIT(0);
        }
        __syncthreads();

        const uint32_t ah_base = smem_u32(&Ah[buf][0][0]);
        const uint32_t bh_base = smem_u32(&Bh[buf][0][0]);

        #pragma unroll
        for (int ks = 0; ks < 2; ++ks) {
            const uint32_t a_off = (uint32_t)(ks * 16 + lane_c) * 2;

            uint32_t ah[4][4];
            #pragma unroll
            for (int mf = 0; mf < 4; ++mf) {
                const uint32_t ro = (uint32_t)((wm + mf * 16 + lane_r) * LDS) * 2;
                ldsm_x4(ah[mf], ah_base + ro + a_off);
            }
            uint32_t bh[4][2];
            #pragma unroll
            for (int np = 0; np < 2; ++np) {
                const uint32_t ro = (uint32_t)((wn + np * 16 + lane_r) * LDS) * 2;
                uint32_t r[4];
                ldsm_x4(r, bh_base + ro + a_off);
                bh[np * 2 + 0][0] = r[0]; bh[np * 2 + 0][1] = r[2];
                bh[np * 2 + 1][0] = r[1]; bh[np * 2 + 1][1] = r[3];
            }

            #pragma unroll
            for (int mf = 0; mf < 4; ++mf)
                #pragma unroll
                for (int nf = 0; nf < 4; ++nf)
                    mma16816(acc[mf][nf], ah[mf], bh[nf]);
        }
        __syncthreads();
    }

    // Epilogue. Thread owns rows (gr, gr+8), cols 2*(lane%4)+{0,1} per fragment.
    const int gr = lane >> 2;
    const int gc = (lane & 3) * 2;
    #pragma unroll
    for (int mf = 0; mf < 4; ++mf) {
        const int row0 = bm + wm + mf * 16 + gr;
        const int row1 = row0 + 8;
        #pragma unroll
        for (int nf = 0; nf < 4; ++nf) {
            const int col = bn + wn + nf * 8 + gc;
            const float bz0 = bias[col], bz1 = bias[col + 1];
            float v00 = acc[mf][nf][0] + bz0, v01 = acc[mf][nf][1] + bz1;
            float v10 = acc[mf][nf][2] + bz0, v11 = acc[mf][nf][3] + bz1;
            if (EPI == 1) {
                v00 = fmaxf(v00, 0.f); v01 = fmaxf(v01, 0.f);
                v10 = fmaxf(v10, 0.f); v11 = fmaxf(v11, 0.f);
                if (row0 < M) {
                    __half2 hh; hh.x = __float2half(v00); hh.y = __float2half(v01);
                    *reinterpret_cast<__half2*>(outh + (size_t)row0 * N + col) = hh;
                }
                if (row1 < M) {
                    __half2 hh; hh.x = __float2half(v10); hh.y = __float2half(v11);
                    *reinterpret_cast<__half2*>(outh + (size_t)row1 * N + col) = hh;
                }
            } else {
                if (row0 < M) {
                    float2 v; v.x = v00; v.y = v01;
                    *reinterpret_cast<float2*>(outf + (size_t)row0 * N + col) = v;
                }
                if (row1 < M) {
                    float2 v; v.x = v10; v.y = v11;
                    *reinterpret_cast<float2*>(outf + (size_t)row1 * N + col) = v;
                }
            }
        }
    }
}

// ---------------------------------------------------------------------------
// Launch
// ---------------------------------------------------------------------------
extern "C" void kernel_launch(void* const* d_in, const int* in_sizes, int n_in,
                              void* d_out, int out_size) {
    const float* x    = (const float*)d_in[0];
    const float* W1a  = (const float*)d_in[1];
    const float* b1a  = (const float*)d_in[2];
    const float* W2a  = (const float*)d_in[3];
    const float* b2a  = (const float*)d_in[4];
    const float* W1b  = (const float*)d_in[5];
    const float* b1b  = (const float*)d_in[6];
    const float* W2b  = (const float*)d_in[7];
    const float* b2b  = (const float*)d_in[8];
    const void*  ei   = d_in[9];

    const int M = N_NODES;
    const int E = in_sizes[9] / 2;

    __half *XH, *A, *B, *WT;
    cudaGetSymbolAddress((void**)&XH, g_xh);
    cudaGetSymbolAddress((void**)&A, g_a);
    cudaGetSymbolAddress((void**)&B, g_b);
    cudaGetSymbolAddress((void**)&WT, g_wt);

    float* out = (float*)d_out;
    const int GY = M_PAD / 128;   // 391

    // Setup (idx dtype + zero deg + weight prep + x->fp16) + CSR build.
    setup_kernel<<<3125, 256>>>((const long long*)ei, W1a, W2a, W1b, W2b, WT, x, XH);
    hist_kernel<<<(E + 255) / 256, 256>>>(ei, E);
    scan_bsum_kernel<<<NB_SCAN, 256>>>(N_NODES);
    scan_boff_kernel<<<1, 256>>>(NB_SCAN, N_NODES);
    scan_write_kernel<<<NB_SCAN, 256>>>(N_NODES);
    fill_kernel<<<(E + 255) / 256, 256>>>(ei, E);

    // ---- Layer 0 ----
    // A = fp16(x + gather(x))    (fp16 reads, fp32 accumulate)
    gather_h128<<<(M * 32 + 255) / 256, 256>>>(XH, A, M);
    // h1 = relu(A @ W1a + b1a) -> fp16 B      [50000,128]@[128,256]
    mma_gemm<1, 128, 256><<<dim3(2, GY), 256>>>(A, WT + 0 * 65536, b1a, nullptr, B, M);
    // h2 = relu(B @ W2a + b2a) -> fp16 A      [50000,256]@[256,256]
    mma_gemm<1, 256, 256><<<dim3(2, GY), 256>>>(B, WT + 1 * 65536, b2a, nullptr, A, M);

    // ---- Layer 1 ----
    // B = fp16(h2 + gather(h2))
    gather_h256<<<(M * 32 + 255) / 256, 256>>>(A, B, M);
    // h3 = relu(B @ W1b + b1b) -> fp16 A      [50000,256]@[256,256]
    mma_gemm<1, 256, 256><<<dim3(2, GY), 256>>>(B, WT + 2 * 65536, b1b, nullptr, A, M);
    // out = A @ W2b + b2b                     [50000,256]@[256,128]
    mma_gemm<0, 256, 128><<<dim3(1, GY), 256>>>(A, WT + 3 * 65536, b2b, out, nullptr, M);
}